// round 1
// baseline (speedup 1.0000x reference)
#include <cuda_runtime.h>

#define DIM 128
#define CDIM 40
#define NLAYER 4
#define NMAX 50000
#define EMAX 800000

// ---------------- device scratch (static: no allocations allowed) ----------
__device__ float g_xbuf[NMAX * DIM];
__device__ float g_gbuf[NMAX * DIM];
__device__ float g_hbuf[NMAX * DIM];
__device__ float g_wfold[DIM * DIM];
__device__ float g_bfold[DIM];
__device__ float g_colsum[DIM];
__device__ float g_colsumsq[DIM];
__device__ float g_mu[DIM];
__device__ float g_scale;
__device__ int   g_rowptr[NMAX + 1];
__device__ int   g_cnt[NMAX];
__device__ int   g_colidx[EMAX];
__device__ float g_vals[EMAX];

// ---------------- small utility kernels ------------------------------------
__global__ void zero_stats_k() {
    int t = threadIdx.x;
    g_colsum[t] = 0.f;
    g_colsumsq[t] = 0.f;
}

__global__ void zero_cnt_k(int n) {
    int i = blockIdx.x * blockDim.x + threadIdx.x;
    if (i < n) g_cnt[i] = 0;
}

// Per-column sum and sum-of-squares over [n, 128]. blockDim = 128 (thread = col).
__global__ void col_stats_k(const float* __restrict__ x, int n) {
    int col = threadIdx.x;
    float s = 0.f, s2 = 0.f;
    for (int r = blockIdx.x; r < n; r += gridDim.x) {
        float v = x[r * DIM + col];
        s += v;
        s2 += v * v;
    }
    atomicAdd(&g_colsum[col], s);
    atomicAdd(&g_colsumsq[col], s2);
}

// Fold BatchNorm into fc_in: W'[d][j] = scale_d*W[d][j];
// b'[j] = b[j] + sum_d (beta_d - mu_d*scale_d) * W[d][j].  1 block x 128 threads.
__global__ void fold_bn_k(const float* __restrict__ W, const float* __restrict__ b,
                          const float* __restrict__ gamma, const float* __restrict__ beta,
                          float n_inv) {
    int j = threadIdx.x;
    __shared__ float sc[DIM], sh[DIM];
    float mu = g_colsum[j] * n_inv;
    float var = g_colsumsq[j] * n_inv - mu * mu;
    float s = gamma[j] * rsqrtf(var + 1e-5f);
    sc[j] = s;
    sh[j] = beta[j] - mu * s;
    __syncthreads();
    float acc = b[j];
    for (int d = 0; d < DIM; d++) {
        float w = W[d * DIM + j];
        g_wfold[d * DIM + j] = sc[d] * w;
        acc += sh[d] * w;
    }
    g_bfold[j] = acc;
}

// PairNorm finalize: mu[j], scale = 1/sqrt(eps + mean row sq-norm of centered).
__global__ void pn_finalize_k(float n_inv) {
    int j = threadIdx.x;
    __shared__ float red[DIM];
    float mu = g_colsum[j] * n_inv;
    g_mu[j] = mu;
    red[j] = g_colsumsq[j] * n_inv - mu * mu;  // per-col contribution to mean rownorm^2
    __syncthreads();
    for (int off = 64; off > 0; off >>= 1) {
        if (j < off) red[j] += red[j + off];
        __syncthreads();
    }
    if (j == 0) g_scale = 1.0f / sqrtf(1e-6f + red[0]);
}

// x = relu((h - mu)*scale) + (addold ? x : 0)   (float4 over n*128 elements)
__global__ void pn_apply_k(const float* __restrict__ h, float* __restrict__ x,
                           int n, int addold) {
    int idx = blockIdx.x * blockDim.x + threadIdx.x;
    int total = n * (DIM / 4);
    if (idx >= total) return;
    int col4 = idx & (DIM / 4 - 1);
    float s = g_scale;
    float4 hv = reinterpret_cast<const float4*>(h)[idx];
    float4 m = reinterpret_cast<const float4*>(g_mu)[col4];
    float4 r;
    r.x = fmaxf((hv.x - m.x) * s, 0.f);
    r.y = fmaxf((hv.y - m.y) * s, 0.f);
    r.z = fmaxf((hv.z - m.z) * s, 0.f);
    r.w = fmaxf((hv.w - m.w) * s, 0.f);
    if (addold) {
        float4 xo = reinterpret_cast<const float4*>(x)[idx];
        r.x += xo.x; r.y += xo.y; r.z += xo.z; r.w += xo.w;
    }
    reinterpret_cast<float4*>(x)[idx] = r;
}

// ---------------- CSR build -------------------------------------------------
__global__ void hist_k(const int* __restrict__ er, int e) {
    int i = blockIdx.x * blockDim.x + threadIdx.x;
    if (i < e) atomicAdd(&g_cnt[er[i]], 1);
}

__global__ __launch_bounds__(1024) void scan_rowptr_k(int n) {
    __shared__ int part[1024];
    int tid = threadIdx.x;
    int chunk = (n + 1023) / 1024;
    int start = tid * chunk;
    int end = start + chunk;
    if (start > n) start = n;
    if (end > n) end = n;
    int s = 0;
    for (int i = start; i < end; i++) s += g_cnt[i];
    part[tid] = s;
    __syncthreads();
    for (int off = 1; off < 1024; off <<= 1) {
        int v = (tid >= off) ? part[tid - off] : 0;
        __syncthreads();
        part[tid] += v;
        __syncthreads();
    }
    int pre = (tid == 0) ? 0 : part[tid - 1];
    for (int i = start; i < end; i++) {
        int c = g_cnt[i];
        g_rowptr[i] = pre;
        pre += c;
    }
    if (tid == 0) g_rowptr[n] = part[1023];
}

__global__ void scatter_k(const int* __restrict__ er, const int* __restrict__ ec,
                          const float* __restrict__ ev, int e) {
    int i = blockIdx.x * blockDim.x + threadIdx.x;
    if (i < e) {
        int r = er[i];
        int pos = g_rowptr[r] + atomicAdd(&g_cnt[r], 1);
        g_colidx[pos] = ec[i];
        g_vals[pos] = ev[i];
    }
}

// ---------------- SPMM (CSR gather, warp per row) --------------------------
__global__ void spmm_k(const float* __restrict__ g, const float* __restrict__ bias,
                       float* __restrict__ h, int n) {
    int warp = (blockIdx.x * blockDim.x + threadIdx.x) >> 5;
    int lane = threadIdx.x & 31;
    if (warp >= n) return;
    int s = g_rowptr[warp];
    int e = g_rowptr[warp + 1];
    float4 acc = make_float4(0.f, 0.f, 0.f, 0.f);
    for (int i = s; i < e; i++) {
        int c = g_colidx[i];
        float v = g_vals[i];
        float4 gv = *reinterpret_cast<const float4*>(&g[c * DIM + lane * 4]);
        acc.x += v * gv.x;
        acc.y += v * gv.y;
        acc.z += v * gv.z;
        acc.w += v * gv.w;
    }
    float4 b4 = *reinterpret_cast<const float4*>(&bias[lane * 4]);
    acc.x += b4.x; acc.y += b4.y; acc.z += b4.z; acc.w += b4.w;
    *reinterpret_cast<float4*>(&h[warp * DIM + lane * 4]) = acc;
}

// ---------------- GEMM [n,128] x [128,128] ----------------------------------
// 128x128 block tile, K=128 fully in smem (128 KB dynamic), 256 threads, 8x8/thread.
__global__ __launch_bounds__(256) void gemm128_k(
    const float* __restrict__ A, const float* __restrict__ B,
    const float* __restrict__ bias, float* __restrict__ C, int n) {
    extern __shared__ float sm[];
    float* As = sm;            // [128][128] row-major [m][k]
    float* Bs = sm + 16384;    // [128][128] row-major [k][n]
    int tid = threadIdx.x;
    int row0 = blockIdx.x * 128;

#pragma unroll
    for (int q = 0; q < 16; q++) {
        int flat = (q * 256 + tid) * 4;
        int r = flat >> 7, c = flat & 127;
        float4 v;
        if (row0 + r < n) v = *reinterpret_cast<const float4*>(&A[(row0 + r) * DIM + c]);
        else v = make_float4(0.f, 0.f, 0.f, 0.f);
        *reinterpret_cast<float4*>(&As[flat]) = v;
        *reinterpret_cast<float4*>(&Bs[flat]) = *reinterpret_cast<const float4*>(&B[flat]);
    }
    __syncthreads();

    int tx = tid & 15, ty = tid >> 4;
    float acc[8][8] = {};
    const float* Ap = As + ty * 8 * 128;
    const float* Bp = Bs + tx * 8;

#pragma unroll 4
    for (int k = 0; k < 128; k++) {
        float a[8], b[8];
#pragma unroll
        for (int i = 0; i < 8; i++) a[i] = Ap[i * 128 + k];
        float4 b0 = *reinterpret_cast<const float4*>(&Bp[k * 128]);
        float4 b1 = *reinterpret_cast<const float4*>(&Bp[k * 128 + 4]);
        b[0] = b0.x; b[1] = b0.y; b[2] = b0.z; b[3] = b0.w;
        b[4] = b1.x; b[5] = b1.y; b[6] = b1.z; b[7] = b1.w;
#pragma unroll
        for (int i = 0; i < 8; i++)
#pragma unroll
            for (int j = 0; j < 8; j++) acc[i][j] += a[i] * b[j];
    }

    float bb[8] = {0.f, 0.f, 0.f, 0.f, 0.f, 0.f, 0.f, 0.f};
    if (bias) {
        float4 c0 = *reinterpret_cast<const float4*>(&bias[tx * 8]);
        float4 c1 = *reinterpret_cast<const float4*>(&bias[tx * 8 + 4]);
        bb[0] = c0.x; bb[1] = c0.y; bb[2] = c0.z; bb[3] = c0.w;
        bb[4] = c1.x; bb[5] = c1.y; bb[6] = c1.z; bb[7] = c1.w;
    }
#pragma unroll
    for (int i = 0; i < 8; i++) {
        int r = row0 + ty * 8 + i;
        if (r < n) {
            float4 o0, o1;
            o0.x = acc[i][0] + bb[0]; o0.y = acc[i][1] + bb[1];
            o0.z = acc[i][2] + bb[2]; o0.w = acc[i][3] + bb[3];
            o1.x = acc[i][4] + bb[4]; o1.y = acc[i][5] + bb[5];
            o1.z = acc[i][6] + bb[6]; o1.w = acc[i][7] + bb[7];
            *reinterpret_cast<float4*>(&C[r * DIM + tx * 8]) = o0;
            *reinterpret_cast<float4*>(&C[r * DIM + tx * 8 + 4]) = o1;
        }
    }
}

// ---------------- output GEMM [n,128] x [128,40] ----------------------------
__global__ __launch_bounds__(256) void gemm_out_k(
    const float* __restrict__ X, const float* __restrict__ W,
    const float* __restrict__ b, float* __restrict__ out, int n) {
    __shared__ float sx[32 * DIM];   // 16 KB
    __shared__ float sw[DIM * CDIM]; // 20 KB
    int tid = threadIdx.x;
    int row0 = blockIdx.x * 32;
    for (int i = tid; i < DIM * CDIM; i += 256) sw[i] = W[i];
#pragma unroll
    for (int q = 0; q < 4; q++) {
        int flat = (q * 256 + tid) * 4;
        int r = flat >> 7, c = flat & 127;
        float4 v;
        if (row0 + r < n) v = *reinterpret_cast<const float4*>(&X[(row0 + r) * DIM + c]);
        else v = make_float4(0.f, 0.f, 0.f, 0.f);
        *reinterpret_cast<float4*>(&sx[flat]) = v;
    }
    __syncthreads();
    int r = tid >> 3;
    int c0 = (tid & 7) * 5;
    float acc[5];
#pragma unroll
    for (int j = 0; j < 5; j++) acc[j] = b[c0 + j];
#pragma unroll 4
    for (int k = 0; k < DIM; k++) {
        float xv = sx[r * DIM + k];
#pragma unroll
        for (int j = 0; j < 5; j++) acc[j] += xv * sw[k * CDIM + c0 + j];
    }
    if (row0 + r < n) {
#pragma unroll
        for (int j = 0; j < 5; j++) out[(row0 + r) * CDIM + c0 + j] = acc[j];
    }
}

// ---------------- launch -----------------------------------------------------
extern "C" void kernel_launch(void* const* d_in, const int* in_sizes, int n_in,
                              void* d_out, int out_size) {
    const float* x      = (const float*)d_in[0];
    const int*   er     = (const int*)d_in[1];
    const int*   ec     = (const int*)d_in[2];
    const float* ev     = (const float*)d_in[3];
    const float* gamma  = (const float*)d_in[4];
    const float* beta   = (const float*)d_in[5];
    const float* fin_w  = (const float*)d_in[6];
    const float* fin_b  = (const float*)d_in[7];
    const float* gc_w   = (const float*)d_in[8];
    const float* gc_b   = (const float*)d_in[9];
    const float* fout_w = (const float*)d_in[10];
    const float* fout_b = (const float*)d_in[11];
    float* out = (float*)d_out;

    int n = in_sizes[0] / DIM;
    int e = in_sizes[1];
    float n_inv = 1.0f / (float)n;

    float *xbuf, *gbuf, *hbuf, *wfold, *bfold;
    cudaGetSymbolAddress((void**)&xbuf, g_xbuf);
    cudaGetSymbolAddress((void**)&gbuf, g_gbuf);
    cudaGetSymbolAddress((void**)&hbuf, g_hbuf);
    cudaGetSymbolAddress((void**)&wfold, g_wfold);
    cudaGetSymbolAddress((void**)&bfold, g_bfold);

    const int GEMM_SMEM = 2 * DIM * DIM * (int)sizeof(float);  // 128 KB
    cudaFuncSetAttribute(gemm128_k, cudaFuncAttributeMaxDynamicSharedMemorySize, GEMM_SMEM);

    // ---- CSR build (amortized across 4 SPMM layers) ----
    zero_cnt_k<<<(n + 255) / 256, 256>>>(n);
    hist_k<<<(e + 255) / 256, 256>>>(er, e);
    scan_rowptr_k<<<1, 1024>>>(n);
    zero_cnt_k<<<(n + 255) / 256, 256>>>(n);
    scatter_k<<<(e + 255) / 256, 256>>>(er, ec, ev, e);

    // ---- BatchNorm stats, fold into fc_in, then fused GEMM ----
    zero_stats_k<<<1, DIM>>>();
    col_stats_k<<<512, DIM>>>(x, n);
    fold_bn_k<<<1, DIM>>>(fin_w, fin_b, gamma, beta, n_inv);
    int gblocks = (n + 127) / 128;
    gemm128_k<<<gblocks, 256, GEMM_SMEM>>>(x, wfold, bfold, xbuf, n);

    // ---- 4 GCN layers ----
    for (int i = 0; i < NLAYER; i++) {
        gemm128_k<<<gblocks, 256, GEMM_SMEM>>>(xbuf, gc_w + i * DIM * DIM, nullptr, gbuf, n);
        spmm_k<<<(n + 7) / 8, 256>>>(gbuf, gc_b + i * DIM, hbuf, n);
        zero_stats_k<<<1, DIM>>>();
        col_stats_k<<<512, DIM>>>(hbuf, n);
        pn_finalize_k<<<1, DIM>>>(n_inv);
        pn_apply_k<<<(n * 32 + 255) / 256, 256>>>(hbuf, xbuf, n, i > 0 ? 1 : 0);
    }

    // ---- output projection ----
    gemm_out_k<<<(n + 31) / 32, 256>>>(xbuf, fout_w, fout_b, out, n);
}